// round 1
// baseline (speedup 1.0000x reference)
#include <cuda_runtime.h>
#include <cstdint>

// RadianceFieldTT: 8-level quantized tensor-train radiance field sampler.
// N = B*R samples, each runs a chain of 7 data-dependent 64x64 matvecs.
// Strategy: one thread per sample, v[64] in registers, all 8 digit-slices of
// the current level's core cached in (padded) shared memory, packed f32x2 FMAs.

#define TT_RANK   64
#define WSTRIDE   4100                    // floats per digit slice: 4096 + 4 pad
                                          // (16400 B == 16 mod 128 -> 8 digits hit
                                          //  8 distinct 16B crossbar lanes)
#define C0STRIDE  68                      // padded core0 slice stride
#define SMC0_OFF  (8 * WSTRIDE)           // 32800 floats
#define SMP_OFF   (SMC0_OFF + 8 * C0STRIDE)  // 33344 floats
#define SM_FLOATS (SMP_OFF + TT_RANK * 4)    // 33600 floats = 134400 B

__device__ __forceinline__ unsigned long long pk2(float lo, float hi) {
    unsigned long long r;
    asm("mov.b64 %0, {%1, %2};" : "=l"(r) : "f"(lo), "f"(hi));
    return r;
}
__device__ __forceinline__ void upk2(unsigned long long v, float& lo, float& hi) {
    asm("mov.b64 {%0, %1}, %2;" : "=f"(lo), "=f"(hi) : "l"(v));
}
// Packed dual-fp32 FMA: full-rate fp32 path on Blackwell (plain FFMA is half rate).
__device__ __forceinline__ unsigned long long ffma2(unsigned long long a,
                                                    unsigned long long b,
                                                    unsigned long long c) {
    unsigned long long d;
    asm("fma.rn.f32x2 %0, %1, %2, %3;" : "=l"(d) : "l"(a), "l"(b), "l"(c));
    return d;
}

__global__ __launch_bounds__(256, 1)
void rftt_kernel(const float* __restrict__ coords,
                 const float* __restrict__ viewdirs,
                 const float* __restrict__ core0,
                 const float* __restrict__ cores,
                 const float* __restrict__ payload,
                 float* __restrict__ out)
{
    extern __shared__ float sm[];
    const int tid  = threadIdx.x;
    const int b    = blockIdx.x;
    const int n    = b * blockDim.x + tid;
    const int ntot = gridDim.x * blockDim.x;

    // ---- per-sample digits + inside mask ----
    const float cx = coords[3 * n + 0];
    const float cy = coords[3 * n + 1];
    const float cz = coords[3 * n + 2];
    const float msk = (fabsf(cx) <= 1.f && fabsf(cy) <= 1.f && fabsf(cz) <= 1.f) ? 1.f : 0.f;
    // (c*0.5+0.5)*256: *0.5 and *256 are exact (powers of 2); single rounding on the
    // add matches XLA's fp32 result bit-for-bit, so digit selection is deterministic.
    const int ix = min(255, max(0, (int)floorf((cx * 0.5f + 0.5f) * 256.f)));
    const int iy = min(255, max(0, (int)floorf((cy * 0.5f + 0.5f) * 256.f)));
    const int iz = min(255, max(0, (int)floorf((cz * 0.5f + 0.5f) * 256.f)));
    unsigned int dig = 0;
#pragma unroll
    for (int l = 0; l < 8; ++l) {
        const int s = 7 - l;
        const unsigned int d = (((ix >> s) & 1) << 2) | (((iy >> s) & 1) << 1) | ((iz >> s) & 1);
        dig |= d << (4 * l);
    }

    // ---- per-CTA precontracted payload: P'[r] = {payload[r,0:9]@sh, [9:18]@sh, [18:27]@sh, payload[r,27]} ----
    // (one CTA == one batch row => viewdirs uniform across the CTA)
    if (tid < TT_RANK) {
        const float* vd = viewdirs + 3 * b;
        const float dx = vd[0], dy = vd[1], dz = vd[2];
        float shv[9];
        shv[0] = 0.28209479177387814f;
        shv[1] = -0.4886025119029199f * dy;
        shv[2] =  0.4886025119029199f * dz;
        shv[3] = -0.4886025119029199f * dx;
        shv[4] =  1.0925484305920792f * dx * dy;
        shv[5] = -1.0925484305920792f * dy * dz;
        shv[6] =  0.31539156525252005f * (2.f * dz * dz - dx * dx - dy * dy);
        shv[7] = -1.0925484305920792f * dx * dz;
        shv[8] =  0.5462742152960396f * (dx * dx - dy * dy);
        const float* pr = payload + tid * 28;
        float s0 = 0.f, s1 = 0.f, s2 = 0.f;
#pragma unroll
        for (int j = 0; j < 9; ++j) {
            s0 = fmaf(pr[j],      shv[j], s0);
            s1 = fmaf(pr[9 + j],  shv[j], s1);
            s2 = fmaf(pr[18 + j], shv[j], s2);
        }
        *(float4*)(sm + SMP_OFF + 4 * tid) = make_float4(s0, s1, s2, pr[27]);
    }
    // core0 (8x64) into padded smem
    for (int j = tid; j < 512; j += blockDim.x) {
        sm[SMC0_OFF + (j >> 6) * C0STRIDE + (j & 63)] = core0[j];
    }

    float v[64];

    // ---- TT chain: levels 1..7, weights staged per level in smem ----
#pragma unroll 1
    for (int l = 1; l < 8; ++l) {
        // cooperative fill: cores[l-1] is [r][m][s] -> smem [m][r][s] padded
        const float4* src = (const float4*)(cores + (size_t)(l - 1) * 32768);
#pragma unroll 8
        for (int j = tid; j < 8192; j += blockDim.x) {
            const float4 w = src[j];
            *(float4*)(sm + ((j >> 4) & 7) * WSTRIDE + (j >> 7) * 64 + (j & 15) * 4) = w;
        }
        __syncthreads();

        if (l == 1) {  // v = core0[digit0, :]
            const int d0 = dig & 7;
            const float* c0 = sm + SMC0_OFF + d0 * C0STRIDE;
#pragma unroll
            for (int q = 0; q < 16; ++q) {
                const float4 t = *(const float4*)(c0 + 4 * q);
                v[4 * q + 0] = t.x; v[4 * q + 1] = t.y;
                v[4 * q + 2] = t.z; v[4 * q + 3] = t.w;
            }
        }

        const float* Wd = sm + ((dig >> (4 * l)) & 7) * WSTRIDE;
        unsigned long long acc[32];
#pragma unroll
        for (int i = 0; i < 32; ++i) acc[i] = 0ull;  // {0.f, 0.f}
#pragma unroll
        for (int r = 0; r < 64; ++r) {
            const unsigned long long vv = pk2(v[r], v[r]);
            const ulonglong2* row = (const ulonglong2*)(Wd + r * 64);
#pragma unroll
            for (int q = 0; q < 16; ++q) {
                const ulonglong2 w = row[q];
                acc[2 * q + 0] = ffma2(w.x, vv, acc[2 * q + 0]);
                acc[2 * q + 1] = ffma2(w.y, vv, acc[2 * q + 1]);
            }
        }
#pragma unroll
        for (int i = 0; i < 32; ++i) upk2(acc[i], v[2 * i], v[2 * i + 1]);
        __syncthreads();
    }

    // ---- epilogue: v @ P' (64x4), mask, store ----
    float o0 = 0.f, o1 = 0.f, o2 = 0.f, o3 = 0.f;
#pragma unroll
    for (int r = 0; r < 64; ++r) {
        const float4 p = *(const float4*)(sm + SMP_OFF + 4 * r);
        o0 = fmaf(v[r], p.x, o0);
        o1 = fmaf(v[r], p.y, o1);
        o2 = fmaf(v[r], p.z, o2);
        o3 = fmaf(v[r], p.w, o3);
    }
    out[3 * n + 0] = o0 * msk;
    out[3 * n + 1] = o1 * msk;
    out[3 * n + 2] = o2 * msk;
    out[3 * ntot + n] = o3 * msk;   // sigma block after rgb block
}

extern "C" void kernel_launch(void* const* d_in, const int* in_sizes, int n_in,
                              void* d_out, int out_size) {
    const float* coords   = (const float*)d_in[0];  // (B,R,3)
    const float* viewdirs = (const float*)d_in[1];  // (B,3)
    const float* core0    = (const float*)d_in[2];  // (1,8,64)
    const float* cores    = (const float*)d_in[3];  // (7,64,8,64)
    const float* payload  = (const float*)d_in[4];  // (64,28)

    const int B = in_sizes[1] / 3;
    const int n_total = in_sizes[0] / 3;
    const int R = n_total / B;   // 256

    const size_t smem = SM_FLOATS * sizeof(float);  // 134400 B
    cudaFuncSetAttribute(rftt_kernel, cudaFuncAttributeMaxDynamicSharedMemorySize, (int)smem);
    rftt_kernel<<<B, R, smem>>>(coords, viewdirs, core0, cores, payload, (float*)d_out);
}

// round 3
// speedup vs baseline: 1.5177x; 1.5177x over previous
#include <cuda_runtime.h>
#include <cstdint>

// RadianceFieldTT: 8-level quantized tensor-train radiance field sampler.
//
// R2 design: owner-computes-by-digit.
//   - v vectors live in SMEM (duplicated {v,v} u64 pairs for direct FFMA2 use).
//   - Each level has 8 candidate 64x64 matrices; warp d holds matrix d entirely
//     in registers (lane j owns output columns 2j, 2j+1 -> 64 packed u64 regs).
//   - Per level, warp d processes exactly the samples whose digit is d
//     (per-level lists built once by counting sort in SMEM).
//   - v reads are warp-uniform LDS.128 (hardware broadcast: 1 wavefront),
//     so smem crossbar traffic drops ~14x vs the per-thread-matvec R1 kernel.

#define THREADS 256
#define RANK    64
#define VST2    66     // u64 entries per v row (64 + 2 pad) -> 528 B, 16 mod 128

// ---- shared memory layout (bytes) ----
#define SM_V2     0                         // 256 rows x VST2 u64 = 135168 B
#define SM_PP     (256 * VST2 * 8)          // 135168: P' float4[64] = 1024 B
#define SM_LIST   (SM_PP + 1024)            // 136192: uint8 list[7][256] = 1792 B
#define SM_CNT    (SM_LIST + 1792)          // 137984: int cnt[7][8] = 224 B
#define SM_OFF    (SM_CNT + 224)            // 138208: int off[7][8] = 224 B
#define SM_BYTES  (SM_OFF + 224)            // 138432 B total

typedef unsigned long long u64;

__device__ __forceinline__ u64 pk2(float lo, float hi) {
    u64 r; asm("mov.b64 %0, {%1, %2};" : "=l"(r) : "f"(lo), "f"(hi)); return r;
}
__device__ __forceinline__ void upk2(u64 v, float& lo, float& hi) {
    asm("mov.b64 {%0, %1}, %2;" : "=f"(lo), "=f"(hi) : "l"(v));
}
__device__ __forceinline__ u64 ffma2(u64 a, u64 b, u64 c) {
    u64 d; asm("fma.rn.f32x2 %0, %1, %2, %3;" : "=l"(d) : "l"(a), "l"(b), "l"(c)); return d;
}
__device__ __forceinline__ u64 add2(u64 a, u64 b) {
    u64 d; asm("add.rn.f32x2 %0, %1, %2;" : "=l"(d) : "l"(a), "l"(b)); return d;
}

__global__ __launch_bounds__(THREADS, 1)
void rftt_kernel(const float* __restrict__ coords,
                 const float* __restrict__ viewdirs,
                 const float* __restrict__ core0,
                 const float* __restrict__ cores,
                 const float* __restrict__ payload,
                 float* __restrict__ out)
{
    extern __shared__ char smb[];
    u64*     v2   = (u64*)(smb + SM_V2);
    float*   pp   = (float*)(smb + SM_PP);
    uint8_t* list = (uint8_t*)(smb + SM_LIST);
    int*     cnt  = (int*)(smb + SM_CNT);
    int*     off  = (int*)(smb + SM_OFF);

    const int tid  = threadIdx.x;
    const int warp = tid >> 5;
    const int lane = tid & 31;
    const int b    = blockIdx.x;
    const int n    = b * THREADS + tid;
    const int ntot = gridDim.x * THREADS;

    // ---- per-sample digits + inside mask ----
    const float cx = coords[3 * n + 0];
    const float cy = coords[3 * n + 1];
    const float cz = coords[3 * n + 2];
    const float msk = (fabsf(cx) <= 1.f && fabsf(cy) <= 1.f && fabsf(cz) <= 1.f) ? 1.f : 0.f;
    const int ix = min(255, max(0, (int)floorf((cx * 0.5f + 0.5f) * 256.f)));
    const int iy = min(255, max(0, (int)floorf((cy * 0.5f + 0.5f) * 256.f)));
    const int iz = min(255, max(0, (int)floorf((cz * 0.5f + 0.5f) * 256.f)));
    unsigned int dig = 0;
#pragma unroll
    for (int l = 0; l < 8; ++l) {
        const int s = 7 - l;
        const unsigned int d = (((ix >> s) & 1) << 2) | (((iy >> s) & 1) << 1) | ((iz >> s) & 1);
        dig |= d << (4 * l);
    }

    // ---- per-CTA precontracted payload P'[r] (CTA == one batch row b) ----
    if (tid < RANK) {
        const float* vd = viewdirs + 3 * b;
        const float dx = vd[0], dy = vd[1], dz = vd[2];
        float shv[9];
        shv[0] = 0.28209479177387814f;
        shv[1] = -0.4886025119029199f * dy;
        shv[2] =  0.4886025119029199f * dz;
        shv[3] = -0.4886025119029199f * dx;
        shv[4] =  1.0925484305920792f * dx * dy;
        shv[5] = -1.0925484305920792f * dy * dz;
        shv[6] =  0.31539156525252005f * (2.f * dz * dz - dx * dx - dy * dy);
        shv[7] = -1.0925484305920792f * dx * dz;
        shv[8] =  0.5462742152960396f * (dx * dx - dy * dy);
        const float* pr = payload + tid * 28;
        float s0 = 0.f, s1 = 0.f, s2 = 0.f;
#pragma unroll
        for (int j = 0; j < 9; ++j) {
            s0 = fmaf(pr[j],      shv[j], s0);
            s1 = fmaf(pr[9 + j],  shv[j], s1);
            s2 = fmaf(pr[18 + j], shv[j], s2);
        }
        *(float4*)(pp + 4 * tid) = make_float4(s0, s1, s2, pr[27]);
    }

    // ---- build per-level digit lists (counting sort, keys known up front) ----
    if (tid < 56) cnt[tid] = 0;
    __syncthreads();
    int rank7[7];
#pragma unroll
    for (int l = 1; l < 8; ++l)
        rank7[l - 1] = atomicAdd(&cnt[(l - 1) * 8 + ((dig >> (4 * l)) & 7)], 1);
    __syncthreads();
    if (tid < 7) {
        int s = 0;
#pragma unroll
        for (int d = 0; d < 8; ++d) { off[tid * 8 + d] = s; s += cnt[tid * 8 + d]; }
    }
    __syncthreads();
#pragma unroll
    for (int l = 1; l < 8; ++l) {
        const int d = (dig >> (4 * l)) & 7;
        list[(l - 1) * 256 + off[(l - 1) * 8 + d] + rank7[l - 1]] = (uint8_t)tid;
    }

    // ---- init: v2[tid][:] = duplicated core0[digit0] ----
    {
        const float4* src = (const float4*)(core0 + (dig & 7) * RANK);
        ulonglong2* dst = (ulonglong2*)(v2 + (size_t)tid * VST2);
#pragma unroll
        for (int q = 0; q < 16; ++q) {
            const float4 t = src[q];
            dst[2 * q + 0] = make_ulonglong2(pk2(t.x, t.x), pk2(t.y, t.y));
            dst[2 * q + 1] = make_ulonglong2(pk2(t.z, t.z), pk2(t.w, t.w));
        }
    }
    __syncthreads();

    // ---- TT chain: levels 1..7, owner-computes by digit ----
#pragma unroll 1
    for (int l = 1; l < 8; ++l) {
        // warp `warp` owns digit == warp; lane owns output cols {2*lane, 2*lane+1}
        // cores layout: [l-1][r][m][s], r stride 512 floats, m stride 64
        u64 wreg[64];
        {
            const float* wp = cores + (size_t)(l - 1) * 32768 + warp * 64 + 2 * lane;
#pragma unroll
            for (int r = 0; r < 64; ++r)
                wreg[r] = *(const u64*)(wp + r * 512);   // LDG.64, coalesced over lanes
        }
        const int base = off[(l - 1) * 8 + warp];
        const int nw   = cnt[(l - 1) * 8 + warp];
        const uint8_t* lst = list + (l - 1) * 256 + base;

#pragma unroll 1
        for (int k = 0; k < nw; ++k) {
            const int i = lst[k];                         // warp-uniform sample id
            const ulonglong2* vrow = (const ulonglong2*)(v2 + (size_t)i * VST2);
            u64 a0 = 0ull, a1 = 0ull, a2 = 0ull, a3 = 0ull;
#pragma unroll
            for (int q = 0; q < 16; ++q) {
                const ulonglong2 vp0 = vrow[2 * q];       // uniform LDS.128 -> broadcast
                const ulonglong2 vp1 = vrow[2 * q + 1];
                a0 = ffma2(wreg[4 * q + 0], vp0.x, a0);
                a1 = ffma2(wreg[4 * q + 1], vp0.y, a1);
                a2 = ffma2(wreg[4 * q + 2], vp1.x, a2);
                a3 = ffma2(wreg[4 * q + 3], vp1.y, a3);
            }
            a0 = add2(a0, a1); a2 = add2(a2, a3); a0 = add2(a0, a2);
            float r0, r1; upk2(a0, r0, r1);
            // write duplicated outputs for cols 2*lane, 2*lane+1 (one STS.128)
            ((ulonglong2*)vrow)[lane] = make_ulonglong2(pk2(r0, r0), pk2(r1, r1));
        }
        __syncthreads();
    }

    // ---- epilogue: thread t -> sample t: out = v @ P' (64x4), mask, store ----
    float o0 = 0.f, o1 = 0.f, o2 = 0.f, o3 = 0.f;
    {
        const float4* vrow = (const float4*)(v2 + (size_t)tid * VST2);
#pragma unroll
        for (int q = 0; q < 32; ++q) {
            const float4 t = vrow[q];                     // {v2q, v2q, v2q+1, v2q+1}
            const float4 pa = *(const float4*)(pp + 4 * (2 * q));
            const float4 pb = *(const float4*)(pp + 4 * (2 * q + 1));
            o0 = fmaf(t.x, pa.x, o0); o1 = fmaf(t.x, pa.y, o1);
            o2 = fmaf(t.x, pa.z, o2); o3 = fmaf(t.x, pa.w, o3);
            o0 = fmaf(t.z, pb.x, o0); o1 = fmaf(t.z, pb.y, o1);
            o2 = fmaf(t.z, pb.z, o2); o3 = fmaf(t.z, pb.w, o3);
        }
    }
    out[3 * n + 0] = o0 * msk;
    out[3 * n + 1] = o1 * msk;
    out[3 * n + 2] = o2 * msk;
    out[3 * ntot + n] = o3 * msk;   // sigma block after rgb block
}

extern "C" void kernel_launch(void* const* d_in, const int* in_sizes, int n_in,
                              void* d_out, int out_size) {
    const float* coords   = (const float*)d_in[0];  // (B,R,3)
    const float* viewdirs = (const float*)d_in[1];  // (B,3)
    const float* core0    = (const float*)d_in[2];  // (1,8,64)
    const float* cores    = (const float*)d_in[3];  // (7,64,8,64)
    const float* payload  = (const float*)d_in[4];  // (64,28)

    const int B = in_sizes[1] / 3;   // 1024 (R = 256 = THREADS)

    cudaFuncSetAttribute(rftt_kernel, cudaFuncAttributeMaxDynamicSharedMemorySize, SM_BYTES);
    rftt_kernel<<<B, THREADS, SM_BYTES>>>(coords, viewdirs, core0, cores, payload, (float*)d_out);
}

// round 4
// speedup vs baseline: 1.8656x; 1.2292x over previous
#include <cuda_runtime.h>
#include <cstdint>

// RadianceFieldTT: 8-level quantized tensor-train radiance field sampler.
//
// R3 design: owner-computes with balanced slices + non-duplicated v.
//   - v vectors (64 floats) live in SMEM, natural layout (r-pairs = u64).
//   - FFMA2 pairs along r: acc = {W[2r][c],W[2r+1][c]} * {v[2r],v[2r+1]}.
//     -> 16 uniform (broadcast) LDS.128 per sample-level instead of 32.
//   - Per level, the 256 samples are bucket-major sorted by digit; warp w
//     processes entries [32w, 32w+32) regardless of bucket, reloading its
//     64x64 weight matrix from L2 when the slice crosses a bucket boundary.
//     -> perfect per-warp balance (no multinomial worst-warp penalty).
//   - Lane j owns output cols j and j+32 -> 2 coalesced STS.32 per sample.

#define THREADS 256
#define RANK    64
#define VSTRIDE 68    // floats per v row: 64 + 4 pad (272 B, 16B-aligned)

// ---- shared memory layout (bytes) ----
#define SM_V      0                          // 256 * 68 * 4 = 69632
#define SM_PP     (256 * VSTRIDE * 4)        // 69632: P' float4[64] = 1024
#define SM_LIST   (SM_PP + 1024)             // 70656: uint8 list[7][256] = 1792
#define SM_CNT    (SM_LIST + 1792)           // 72448: int cnt[7][8] = 224
#define SM_OFF    (SM_CNT + 224)             // 72672: int off[7][9] = 252
#define SM_BYTES  (SM_OFF + 256)             // 72928 B total

typedef unsigned long long u64;

__device__ __forceinline__ u64 pk2(float lo, float hi) {
    u64 r; asm("mov.b64 %0, {%1, %2};" : "=l"(r) : "f"(lo), "f"(hi)); return r;
}
__device__ __forceinline__ void upk2(u64 v, float& lo, float& hi) {
    asm("mov.b64 {%0, %1}, %2;" : "=f"(lo), "=f"(hi) : "l"(v));
}
__device__ __forceinline__ u64 ffma2(u64 a, u64 b, u64 c) {
    u64 d; asm("fma.rn.f32x2 %0, %1, %2, %3;" : "=l"(d) : "l"(a), "l"(b), "l"(c)); return d;
}
__device__ __forceinline__ u64 add2(u64 a, u64 b) {
    u64 d; asm("add.rn.f32x2 %0, %1, %2;" : "=l"(d) : "l"(a), "l"(b)); return d;
}

__global__ __launch_bounds__(THREADS, 1)
void rftt_kernel(const float* __restrict__ coords,
                 const float* __restrict__ viewdirs,
                 const float* __restrict__ core0,
                 const float* __restrict__ cores,
                 const float* __restrict__ payload,
                 float* __restrict__ out)
{
    extern __shared__ char smb[];
    float*   v2f  = (float*)(smb + SM_V);
    float*   pp   = (float*)(smb + SM_PP);
    uint8_t* list = (uint8_t*)(smb + SM_LIST);
    int*     cnt  = (int*)(smb + SM_CNT);
    int*     off  = (int*)(smb + SM_OFF);

    const int tid  = threadIdx.x;
    const int warp = tid >> 5;
    const int lane = tid & 31;
    const int b    = blockIdx.x;
    const int n    = b * THREADS + tid;
    const int ntot = gridDim.x * THREADS;

    // ---- per-sample digits + inside mask ----
    const float cx = coords[3 * n + 0];
    const float cy = coords[3 * n + 1];
    const float cz = coords[3 * n + 2];
    const float msk = (fabsf(cx) <= 1.f && fabsf(cy) <= 1.f && fabsf(cz) <= 1.f) ? 1.f : 0.f;
    const int ix = min(255, max(0, (int)floorf((cx * 0.5f + 0.5f) * 256.f)));
    const int iy = min(255, max(0, (int)floorf((cy * 0.5f + 0.5f) * 256.f)));
    const int iz = min(255, max(0, (int)floorf((cz * 0.5f + 0.5f) * 256.f)));
    unsigned int dig = 0;
#pragma unroll
    for (int l = 0; l < 8; ++l) {
        const int s = 7 - l;
        const unsigned int d = (((ix >> s) & 1) << 2) | (((iy >> s) & 1) << 1) | ((iz >> s) & 1);
        dig |= d << (4 * l);
    }

    // ---- per-CTA precontracted payload P'[r] (CTA == one batch row b) ----
    if (tid < RANK) {
        const float* vd = viewdirs + 3 * b;
        const float dx = vd[0], dy = vd[1], dz = vd[2];
        float shv[9];
        shv[0] = 0.28209479177387814f;
        shv[1] = -0.4886025119029199f * dy;
        shv[2] =  0.4886025119029199f * dz;
        shv[3] = -0.4886025119029199f * dx;
        shv[4] =  1.0925484305920792f * dx * dy;
        shv[5] = -1.0925484305920792f * dy * dz;
        shv[6] =  0.31539156525252005f * (2.f * dz * dz - dx * dx - dy * dy);
        shv[7] = -1.0925484305920792f * dx * dz;
        shv[8] =  0.5462742152960396f * (dx * dx - dy * dy);
        const float* pr = payload + tid * 28;
        float s0 = 0.f, s1 = 0.f, s2 = 0.f;
#pragma unroll
        for (int j = 0; j < 9; ++j) {
            s0 = fmaf(pr[j],      shv[j], s0);
            s1 = fmaf(pr[9 + j],  shv[j], s1);
            s2 = fmaf(pr[18 + j], shv[j], s2);
        }
        *(float4*)(pp + 4 * tid) = make_float4(s0, s1, s2, pr[27]);
    }

    // ---- init v row: v2f[tid][:] = core0[digit0] ----
    {
        const float4* src = (const float4*)(core0 + (dig & 7) * RANK);
        float4* dst = (float4*)(v2f + (size_t)tid * VSTRIDE);
#pragma unroll
        for (int q = 0; q < 16; ++q) dst[q] = src[q];
    }

    // ---- counting sort: per-level digit lists (bucket-major) ----
    if (tid < 56) cnt[tid] = 0;
    __syncthreads();
    int rank7[7];
#pragma unroll
    for (int l = 1; l < 8; ++l)
        rank7[l - 1] = atomicAdd(&cnt[(l - 1) * 8 + ((dig >> (4 * l)) & 7)], 1);
    __syncthreads();
    if (tid < 7) {
        int s = 0;
#pragma unroll
        for (int d = 0; d < 8; ++d) { off[tid * 9 + d] = s; s += cnt[tid * 8 + d]; }
        off[tid * 9 + 8] = 256;
    }
    __syncthreads();
#pragma unroll
    for (int l = 1; l < 8; ++l) {
        const int d = (dig >> (4 * l)) & 7;
        list[(l - 1) * 256 + off[(l - 1) * 9 + d] + rank7[l - 1]] = (uint8_t)tid;
    }
    __syncthreads();

    // ---- TT chain: levels 1..7, balanced slices of the bucket-major list ----
#pragma unroll 1
    for (int l = 1; l < 8; ++l) {
        const int* offL = off + (l - 1) * 9;
        const uint8_t* lst = list + (l - 1) * 256;
        const float* wlev = cores + (size_t)(l - 1) * 32768;   // [r][m][c]: r*512 + m*64 + c

        const int k0 = warp * 32;
        const int k1 = k0 + 32;

        int d = 0;
        while (offL[d + 1] <= k0) ++d;
        bool need = true;

        u64 wa[32], wb[32];   // lane's cols: lane and lane+32, paired along r

#pragma unroll 1
        for (int k = k0; k < k1; ++k) {
            while (k >= offL[d + 1]) { ++d; need = true; }
            if (need) {
                const float* wd = wlev + d * 64;
#pragma unroll
                for (int q = 0; q < 32; ++q) {
                    const float w00 = wd[(2 * q) * 512 + lane];
                    const float w01 = wd[(2 * q + 1) * 512 + lane];
                    const float w10 = wd[(2 * q) * 512 + lane + 32];
                    const float w11 = wd[(2 * q + 1) * 512 + lane + 32];
                    wa[q] = pk2(w00, w01);
                    wb[q] = pk2(w10, w11);
                }
                need = false;
            }

            const int i = lst[k];                         // warp-uniform sample id
            const ulonglong2* vrow = (const ulonglong2*)(v2f + (size_t)i * VSTRIDE);
            u64 a0 = 0ull, a1 = 0ull, b0 = 0ull, b1 = 0ull;
#pragma unroll
            for (int q = 0; q < 16; ++q) {
                const ulonglong2 vp = vrow[q];            // uniform LDS.128 -> broadcast
                a0 = ffma2(wa[2 * q + 0], vp.x, a0);
                b0 = ffma2(wb[2 * q + 0], vp.x, b0);
                a1 = ffma2(wa[2 * q + 1], vp.y, a1);
                b1 = ffma2(wb[2 * q + 1], vp.y, b1);
            }
            float ra0, ra1, rb0, rb1;
            upk2(add2(a0, a1), ra0, ra1);
            upk2(add2(b0, b1), rb0, rb1);
            v2f[(size_t)i * VSTRIDE + lane]      = ra0 + ra1;   // coalesced STS.32
            v2f[(size_t)i * VSTRIDE + 32 + lane] = rb0 + rb1;
        }
        __syncthreads();
    }

    // ---- epilogue: thread t -> sample t: out = v @ P' (64x4), mask, store ----
    float o0 = 0.f, o1 = 0.f, o2 = 0.f, o3 = 0.f;
    {
        const float4* vrow = (const float4*)(v2f + (size_t)tid * VSTRIDE);
#pragma unroll
        for (int q = 0; q < 16; ++q) {
            const float4 t = vrow[q];
            const float4 p0 = *(const float4*)(pp + 4 * (4 * q + 0));
            const float4 p1 = *(const float4*)(pp + 4 * (4 * q + 1));
            const float4 p2 = *(const float4*)(pp + 4 * (4 * q + 2));
            const float4 p3 = *(const float4*)(pp + 4 * (4 * q + 3));
            o0 = fmaf(t.x, p0.x, o0); o1 = fmaf(t.x, p0.y, o1);
            o2 = fmaf(t.x, p0.z, o2); o3 = fmaf(t.x, p0.w, o3);
            o0 = fmaf(t.y, p1.x, o0); o1 = fmaf(t.y, p1.y, o1);
            o2 = fmaf(t.y, p1.z, o2); o3 = fmaf(t.y, p1.w, o3);
            o0 = fmaf(t.z, p2.x, o0); o1 = fmaf(t.z, p2.y, o1);
            o2 = fmaf(t.z, p2.z, o2); o3 = fmaf(t.z, p2.w, o3);
            o0 = fmaf(t.w, p3.x, o0); o1 = fmaf(t.w, p3.y, o1);
            o2 = fmaf(t.w, p3.z, o2); o3 = fmaf(t.w, p3.w, o3);
        }
    }
    out[3 * n + 0] = o0 * msk;
    out[3 * n + 1] = o1 * msk;
    out[3 * n + 2] = o2 * msk;
    out[3 * ntot + n] = o3 * msk;   // sigma block after rgb block
}

extern "C" void kernel_launch(void* const* d_in, const int* in_sizes, int n_in,
                              void* d_out, int out_size) {
    const float* coords   = (const float*)d_in[0];  // (B,R,3)
    const float* viewdirs = (const float*)d_in[1];  // (B,3)
    const float* core0    = (const float*)d_in[2];  // (1,8,64)
    const float* cores    = (const float*)d_in[3];  // (7,64,8,64)
    const float* payload  = (const float*)d_in[4];  // (64,28)

    const int B = in_sizes[1] / 3;   // 1024 (R = 256 = THREADS)

    cudaFuncSetAttribute(rftt_kernel, cudaFuncAttributeMaxDynamicSharedMemorySize, SM_BYTES);
    rftt_kernel<<<B, THREADS, SM_BYTES>>>(coords, viewdirs, core0, cores, payload, (float*)d_out);
}

// round 5
// speedup vs baseline: 2.1346x; 1.1442x over previous
#include <cuda_runtime.h>
#include <cstdint>

// RadianceFieldTT: 8-level quantized tensor-train radiance field sampler.
//
// R4 design: R3 (owner-computes, balanced slices, non-duplicated v) +
//   TWO samples in flight per warp sharing the same in-register weight matrix.
//   8 independent FFMA2 accumulator chains per warp hide LDS/FFMA latency at
//   the fixed 2-warps-per-SMSP occupancy (weights pin 128 regs -> 1 CTA/SM).

#define THREADS 256
#define RANK    64
#define VSTRIDE 68    // floats per v row: 64 + 4 pad (272 B, 16B-aligned)

// ---- shared memory layout (bytes) ----
#define SM_V      0                          // 256 * 68 * 4 = 69632
#define SM_PP     (256 * VSTRIDE * 4)        // 69632: P' float4[64] = 1024
#define SM_LIST   (SM_PP + 1024)             // 70656: uint8 list[7][256] = 1792
#define SM_CNT    (SM_LIST + 1792)           // 72448: int cnt[7][8] = 224
#define SM_OFF    (SM_CNT + 224)             // 72672: int off[7][9] = 252
#define SM_BYTES  (SM_OFF + 256)             // 72928 B total

typedef unsigned long long u64;

__device__ __forceinline__ u64 pk2(float lo, float hi) {
    u64 r; asm("mov.b64 %0, {%1, %2};" : "=l"(r) : "f"(lo), "f"(hi)); return r;
}
__device__ __forceinline__ void upk2(u64 v, float& lo, float& hi) {
    asm("mov.b64 {%0, %1}, %2;" : "=f"(lo), "=f"(hi) : "l"(v));
}
__device__ __forceinline__ u64 ffma2(u64 a, u64 b, u64 c) {
    u64 d; asm("fma.rn.f32x2 %0, %1, %2, %3;" : "=l"(d) : "l"(a), "l"(b), "l"(c)); return d;
}
__device__ __forceinline__ u64 add2(u64 a, u64 b) {
    u64 d; asm("add.rn.f32x2 %0, %1, %2;" : "=l"(d) : "l"(a), "l"(b)); return d;
}

__global__ __launch_bounds__(THREADS, 1)
void rftt_kernel(const float* __restrict__ coords,
                 const float* __restrict__ viewdirs,
                 const float* __restrict__ core0,
                 const float* __restrict__ cores,
                 const float* __restrict__ payload,
                 float* __restrict__ out)
{
    extern __shared__ char smb[];
    float*   v2f  = (float*)(smb + SM_V);
    float*   pp   = (float*)(smb + SM_PP);
    uint8_t* list = (uint8_t*)(smb + SM_LIST);
    int*     cnt  = (int*)(smb + SM_CNT);
    int*     off  = (int*)(smb + SM_OFF);

    const int tid  = threadIdx.x;
    const int warp = tid >> 5;
    const int lane = tid & 31;
    const int b    = blockIdx.x;
    const int n    = b * THREADS + tid;
    const int ntot = gridDim.x * THREADS;

    // ---- per-sample digits + inside mask ----
    const float cx = coords[3 * n + 0];
    const float cy = coords[3 * n + 1];
    const float cz = coords[3 * n + 2];
    const float msk = (fabsf(cx) <= 1.f && fabsf(cy) <= 1.f && fabsf(cz) <= 1.f) ? 1.f : 0.f;
    const int ix = min(255, max(0, (int)floorf((cx * 0.5f + 0.5f) * 256.f)));
    const int iy = min(255, max(0, (int)floorf((cy * 0.5f + 0.5f) * 256.f)));
    const int iz = min(255, max(0, (int)floorf((cz * 0.5f + 0.5f) * 256.f)));
    unsigned int dig = 0;
#pragma unroll
    for (int l = 0; l < 8; ++l) {
        const int s = 7 - l;
        const unsigned int d = (((ix >> s) & 1) << 2) | (((iy >> s) & 1) << 1) | ((iz >> s) & 1);
        dig |= d << (4 * l);
    }

    // ---- per-CTA precontracted payload P'[r] (CTA == one batch row b) ----
    if (tid < RANK) {
        const float* vd = viewdirs + 3 * b;
        const float dx = vd[0], dy = vd[1], dz = vd[2];
        float shv[9];
        shv[0] = 0.28209479177387814f;
        shv[1] = -0.4886025119029199f * dy;
        shv[2] =  0.4886025119029199f * dz;
        shv[3] = -0.4886025119029199f * dx;
        shv[4] =  1.0925484305920792f * dx * dy;
        shv[5] = -1.0925484305920792f * dy * dz;
        shv[6] =  0.31539156525252005f * (2.f * dz * dz - dx * dx - dy * dy);
        shv[7] = -1.0925484305920792f * dx * dz;
        shv[8] =  0.5462742152960396f * (dx * dx - dy * dy);
        const float* pr = payload + tid * 28;
        float s0 = 0.f, s1 = 0.f, s2 = 0.f;
#pragma unroll
        for (int j = 0; j < 9; ++j) {
            s0 = fmaf(pr[j],      shv[j], s0);
            s1 = fmaf(pr[9 + j],  shv[j], s1);
            s2 = fmaf(pr[18 + j], shv[j], s2);
        }
        *(float4*)(pp + 4 * tid) = make_float4(s0, s1, s2, pr[27]);
    }

    // ---- init v row: v2f[tid][:] = core0[digit0] ----
    {
        const float4* src = (const float4*)(core0 + (dig & 7) * RANK);
        float4* dst = (float4*)(v2f + (size_t)tid * VSTRIDE);
#pragma unroll
        for (int q = 0; q < 16; ++q) dst[q] = src[q];
    }

    // ---- counting sort: per-level digit lists (bucket-major) ----
    if (tid < 56) cnt[tid] = 0;
    __syncthreads();
    int rank7[7];
#pragma unroll
    for (int l = 1; l < 8; ++l)
        rank7[l - 1] = atomicAdd(&cnt[(l - 1) * 8 + ((dig >> (4 * l)) & 7)], 1);
    __syncthreads();
    if (tid < 7) {
        int s = 0;
#pragma unroll
        for (int d = 0; d < 8; ++d) { off[tid * 9 + d] = s; s += cnt[tid * 8 + d]; }
        off[tid * 9 + 8] = 256;
    }
    __syncthreads();
#pragma unroll
    for (int l = 1; l < 8; ++l) {
        const int d = (dig >> (4 * l)) & 7;
        list[(l - 1) * 256 + off[(l - 1) * 9 + d] + rank7[l - 1]] = (uint8_t)tid;
    }
    __syncthreads();

    // ---- TT chain: levels 1..7 ----
#pragma unroll 1
    for (int l = 1; l < 8; ++l) {
        const int* offL = off + (l - 1) * 9;
        const uint8_t* lst = list + (l - 1) * 256;
        const float* wlev = cores + (size_t)(l - 1) * 32768;   // [r][m][c]: r*512 + m*64 + c

        const int k0 = warp * 32;
        const int k1 = k0 + 32;

        int d = 0;
        while (offL[d + 1] <= k0) ++d;

        u64 wa[32], wb[32];   // lane's cols: lane and lane+32, paired along r
        {
            const float* wd = wlev + d * 64;
#pragma unroll
            for (int q = 0; q < 32; ++q) {
                wa[q] = pk2(wd[(2 * q) * 512 + lane],      wd[(2 * q + 1) * 512 + lane]);
                wb[q] = pk2(wd[(2 * q) * 512 + lane + 32], wd[(2 * q + 1) * 512 + lane + 32]);
            }
        }

        int k = k0;
#pragma unroll 1
        while (k < k1) {
            if (k >= offL[d + 1]) {            // crossed into next non-empty bucket
                do { ++d; } while (k >= offL[d + 1]);
                const float* wd = wlev + d * 64;
#pragma unroll
                for (int q = 0; q < 32; ++q) {
                    wa[q] = pk2(wd[(2 * q) * 512 + lane],      wd[(2 * q + 1) * 512 + lane]);
                    wb[q] = pk2(wd[(2 * q) * 512 + lane + 32], wd[(2 * q + 1) * 512 + lane + 32]);
                }
            }
            const int run_end = min(k1, offL[d + 1]);

            // dual-sample pairs within this same-weight run
#pragma unroll 1
            for (; k + 1 < run_end; k += 2) {
                const int iA = lst[k];
                const int iB = lst[k + 1];
                const ulonglong2* vA = (const ulonglong2*)(v2f + (size_t)iA * VSTRIDE);
                const ulonglong2* vB = (const ulonglong2*)(v2f + (size_t)iB * VSTRIDE);
                u64 a0 = 0ull, a1 = 0ull, b0 = 0ull, b1 = 0ull;
                u64 c0 = 0ull, c1 = 0ull, e0 = 0ull, e1 = 0ull;
#pragma unroll
                for (int q = 0; q < 16; ++q) {
                    const ulonglong2 pA = vA[q];          // uniform LDS.128 (broadcast)
                    const ulonglong2 pB = vB[q];
                    a0 = ffma2(wa[2 * q + 0], pA.x, a0);
                    c0 = ffma2(wa[2 * q + 0], pB.x, c0);
                    b0 = ffma2(wb[2 * q + 0], pA.x, b0);
                    e0 = ffma2(wb[2 * q + 0], pB.x, e0);
                    a1 = ffma2(wa[2 * q + 1], pA.y, a1);
                    c1 = ffma2(wa[2 * q + 1], pB.y, c1);
                    b1 = ffma2(wb[2 * q + 1], pA.y, b1);
                    e1 = ffma2(wb[2 * q + 1], pB.y, e1);
                }
                float x0, x1, y0, y1;
                upk2(add2(a0, a1), x0, x1);
                upk2(add2(b0, b1), y0, y1);
                v2f[(size_t)iA * VSTRIDE + lane]      = x0 + x1;
                v2f[(size_t)iA * VSTRIDE + 32 + lane] = y0 + y1;
                upk2(add2(c0, c1), x0, x1);
                upk2(add2(e0, e1), y0, y1);
                v2f[(size_t)iB * VSTRIDE + lane]      = x0 + x1;
                v2f[(size_t)iB * VSTRIDE + 32 + lane] = y0 + y1;
            }
            // odd leftover in this run
            if (k < run_end) {
                const int iA = lst[k];
                const ulonglong2* vA = (const ulonglong2*)(v2f + (size_t)iA * VSTRIDE);
                u64 a0 = 0ull, a1 = 0ull, b0 = 0ull, b1 = 0ull;
#pragma unroll
                for (int q = 0; q < 16; ++q) {
                    const ulonglong2 pA = vA[q];
                    a0 = ffma2(wa[2 * q + 0], pA.x, a0);
                    b0 = ffma2(wb[2 * q + 0], pA.x, b0);
                    a1 = ffma2(wa[2 * q + 1], pA.y, a1);
                    b1 = ffma2(wb[2 * q + 1], pA.y, b1);
                }
                float x0, x1, y0, y1;
                upk2(add2(a0, a1), x0, x1);
                upk2(add2(b0, b1), y0, y1);
                v2f[(size_t)iA * VSTRIDE + lane]      = x0 + x1;
                v2f[(size_t)iA * VSTRIDE + 32 + lane] = y0 + y1;
                ++k;
            }
        }
        __syncthreads();
    }

    // ---- epilogue: thread t -> sample t: out = v @ P' (64x4), mask, store ----
    float o0 = 0.f, o1 = 0.f, o2 = 0.f, o3 = 0.f;
    {
        const float4* vrow = (const float4*)(v2f + (size_t)tid * VSTRIDE);
#pragma unroll
        for (int q = 0; q < 16; ++q) {
            const float4 t = vrow[q];
            const float4 p0 = *(const float4*)(pp + 4 * (4 * q + 0));
            const float4 p1 = *(const float4*)(pp + 4 * (4 * q + 1));
            const float4 p2 = *(const float4*)(pp + 4 * (4 * q + 2));
            const float4 p3 = *(const float4*)(pp + 4 * (4 * q + 3));
            o0 = fmaf(t.x, p0.x, o0); o1 = fmaf(t.x, p0.y, o1);
            o2 = fmaf(t.x, p0.z, o2); o3 = fmaf(t.x, p0.w, o3);
            o0 = fmaf(t.y, p1.x, o0); o1 = fmaf(t.y, p1.y, o1);
            o2 = fmaf(t.y, p1.z, o2); o3 = fmaf(t.y, p1.w, o3);
            o0 = fmaf(t.z, p2.x, o0); o1 = fmaf(t.z, p2.y, o1);
            o2 = fmaf(t.z, p2.z, o2); o3 = fmaf(t.z, p2.w, o3);
            o0 = fmaf(t.w, p3.x, o0); o1 = fmaf(t.w, p3.y, o1);
            o2 = fmaf(t.w, p3.z, o2); o3 = fmaf(t.w, p3.w, o3);
        }
    }
    out[3 * n + 0] = o0 * msk;
    out[3 * n + 1] = o1 * msk;
    out[3 * n + 2] = o2 * msk;
    out[3 * ntot + n] = o3 * msk;   // sigma block after rgb block
}

extern "C" void kernel_launch(void* const* d_in, const int* in_sizes, int n_in,
                              void* d_out, int out_size) {
    const float* coords   = (const float*)d_in[0];  // (B,R,3)
    const float* viewdirs = (const float*)d_in[1];  // (B,3)
    const float* core0    = (const float*)d_in[2];  // (1,8,64)
    const float* cores    = (const float*)d_in[3];  // (7,64,8,64)
    const float* payload  = (const float*)d_in[4];  // (64,28)

    const int B = in_sizes[1] / 3;   // 1024 (R = 256 = THREADS)

    cudaFuncSetAttribute(rftt_kernel, cudaFuncAttributeMaxDynamicSharedMemorySize, SM_BYTES);
    rftt_kernel<<<B, THREADS, SM_BYTES>>>(coords, viewdirs, core0, cores, payload, (float*)d_out);
}

// round 6
// speedup vs baseline: 2.1394x; 1.0022x over previous
#include <cuda_runtime.h>
#include <cstdint>

// RadianceFieldTT: 8-level quantized tensor-train radiance field sampler.
//
// R4 design: R3 (owner-computes, balanced slices, non-duplicated v) +
//   TWO samples in flight per warp sharing the same in-register weight matrix.
//   8 independent FFMA2 accumulator chains per warp hide LDS/FFMA latency at
//   the fixed 2-warps-per-SMSP occupancy (weights pin 128 regs -> 1 CTA/SM).

#define THREADS 256
#define RANK    64
#define VSTRIDE 68    // floats per v row: 64 + 4 pad (272 B, 16B-aligned)

// ---- shared memory layout (bytes) ----
#define SM_V      0                          // 256 * 68 * 4 = 69632
#define SM_PP     (256 * VSTRIDE * 4)        // 69632: P' float4[64] = 1024
#define SM_LIST   (SM_PP + 1024)             // 70656: uint8 list[7][256] = 1792
#define SM_CNT    (SM_LIST + 1792)           // 72448: int cnt[7][8] = 224
#define SM_OFF    (SM_CNT + 224)             // 72672: int off[7][9] = 252
#define SM_BYTES  (SM_OFF + 256)             // 72928 B total

typedef unsigned long long u64;

__device__ __forceinline__ u64 pk2(float lo, float hi) {
    u64 r; asm("mov.b64 %0, {%1, %2};" : "=l"(r) : "f"(lo), "f"(hi)); return r;
}
__device__ __forceinline__ void upk2(u64 v, float& lo, float& hi) {
    asm("mov.b64 {%0, %1}, %2;" : "=f"(lo), "=f"(hi) : "l"(v));
}
__device__ __forceinline__ u64 ffma2(u64 a, u64 b, u64 c) {
    u64 d; asm("fma.rn.f32x2 %0, %1, %2, %3;" : "=l"(d) : "l"(a), "l"(b), "l"(c)); return d;
}
__device__ __forceinline__ u64 add2(u64 a, u64 b) {
    u64 d; asm("add.rn.f32x2 %0, %1, %2;" : "=l"(d) : "l"(a), "l"(b)); return d;
}

__global__ __launch_bounds__(THREADS, 1)
void rftt_kernel(const float* __restrict__ coords,
                 const float* __restrict__ viewdirs,
                 const float* __restrict__ core0,
                 const float* __restrict__ cores,
                 const float* __restrict__ payload,
                 float* __restrict__ out)
{
    extern __shared__ char smb[];
    float*   v2f  = (float*)(smb + SM_V);
    float*   pp   = (float*)(smb + SM_PP);
    uint8_t* list = (uint8_t*)(smb + SM_LIST);
    int*     cnt  = (int*)(smb + SM_CNT);
    int*     off  = (int*)(smb + SM_OFF);

    const int tid  = threadIdx.x;
    const int warp = tid >> 5;
    const int lane = tid & 31;
    const int b    = blockIdx.x;
    const int n    = b * THREADS + tid;
    const int ntot = gridDim.x * THREADS;

    // ---- per-sample digits + inside mask ----
    const float cx = coords[3 * n + 0];
    const float cy = coords[3 * n + 1];
    const float cz = coords[3 * n + 2];
    const float msk = (fabsf(cx) <= 1.f && fabsf(cy) <= 1.f && fabsf(cz) <= 1.f) ? 1.f : 0.f;
    const int ix = min(255, max(0, (int)floorf((cx * 0.5f + 0.5f) * 256.f)));
    const int iy = min(255, max(0, (int)floorf((cy * 0.5f + 0.5f) * 256.f)));
    const int iz = min(255, max(0, (int)floorf((cz * 0.5f + 0.5f) * 256.f)));
    unsigned int dig = 0;
#pragma unroll
    for (int l = 0; l < 8; ++l) {
        const int s = 7 - l;
        const unsigned int d = (((ix >> s) & 1) << 2) | (((iy >> s) & 1) << 1) | ((iz >> s) & 1);
        dig |= d << (4 * l);
    }

    // ---- per-CTA precontracted payload P'[r] (CTA == one batch row b) ----
    if (tid < RANK) {
        const float* vd = viewdirs + 3 * b;
        const float dx = vd[0], dy = vd[1], dz = vd[2];
        float shv[9];
        shv[0] = 0.28209479177387814f;
        shv[1] = -0.4886025119029199f * dy;
        shv[2] =  0.4886025119029199f * dz;
        shv[3] = -0.4886025119029199f * dx;
        shv[4] =  1.0925484305920792f * dx * dy;
        shv[5] = -1.0925484305920792f * dy * dz;
        shv[6] =  0.31539156525252005f * (2.f * dz * dz - dx * dx - dy * dy);
        shv[7] = -1.0925484305920792f * dx * dz;
        shv[8] =  0.5462742152960396f * (dx * dx - dy * dy);
        const float* pr = payload + tid * 28;
        float s0 = 0.f, s1 = 0.f, s2 = 0.f;
#pragma unroll
        for (int j = 0; j < 9; ++j) {
            s0 = fmaf(pr[j],      shv[j], s0);
            s1 = fmaf(pr[9 + j],  shv[j], s1);
            s2 = fmaf(pr[18 + j], shv[j], s2);
        }
        *(float4*)(pp + 4 * tid) = make_float4(s0, s1, s2, pr[27]);
    }

    // ---- init v row: v2f[tid][:] = core0[digit0] ----
    {
        const float4* src = (const float4*)(core0 + (dig & 7) * RANK);
        float4* dst = (float4*)(v2f + (size_t)tid * VSTRIDE);
#pragma unroll
        for (int q = 0; q < 16; ++q) dst[q] = src[q];
    }

    // ---- counting sort: per-level digit lists (bucket-major) ----
    if (tid < 56) cnt[tid] = 0;
    __syncthreads();
    int rank7[7];
#pragma unroll
    for (int l = 1; l < 8; ++l)
        rank7[l - 1] = atomicAdd(&cnt[(l - 1) * 8 + ((dig >> (4 * l)) & 7)], 1);
    __syncthreads();
    if (tid < 7) {
        int s = 0;
#pragma unroll
        for (int d = 0; d < 8; ++d) { off[tid * 9 + d] = s; s += cnt[tid * 8 + d]; }
        off[tid * 9 + 8] = 256;
    }
    __syncthreads();
#pragma unroll
    for (int l = 1; l < 8; ++l) {
        const int d = (dig >> (4 * l)) & 7;
        list[(l - 1) * 256 + off[(l - 1) * 9 + d] + rank7[l - 1]] = (uint8_t)tid;
    }
    __syncthreads();

    // ---- TT chain: levels 1..7 ----
#pragma unroll 1
    for (int l = 1; l < 8; ++l) {
        const int* offL = off + (l - 1) * 9;
        const uint8_t* lst = list + (l - 1) * 256;
        const float* wlev = cores + (size_t)(l - 1) * 32768;   // [r][m][c]: r*512 + m*64 + c

        const int k0 = warp * 32;
        const int k1 = k0 + 32;

        int d = 0;
        while (offL[d + 1] <= k0) ++d;

        u64 wa[32], wb[32];   // lane's cols: lane and lane+32, paired along r
        {
            const float* wd = wlev + d * 64;
#pragma unroll
            for (int q = 0; q < 32; ++q) {
                wa[q] = pk2(wd[(2 * q) * 512 + lane],      wd[(2 * q + 1) * 512 + lane]);
                wb[q] = pk2(wd[(2 * q) * 512 + lane + 32], wd[(2 * q + 1) * 512 + lane + 32]);
            }
        }

        int k = k0;
#pragma unroll 1
        while (k < k1) {
            if (k >= offL[d + 1]) {            // crossed into next non-empty bucket
                do { ++d; } while (k >= offL[d + 1]);
                const float* wd = wlev + d * 64;
#pragma unroll
                for (int q = 0; q < 32; ++q) {
                    wa[q] = pk2(wd[(2 * q) * 512 + lane],      wd[(2 * q + 1) * 512 + lane]);
                    wb[q] = pk2(wd[(2 * q) * 512 + lane + 32], wd[(2 * q + 1) * 512 + lane + 32]);
                }
            }
            const int run_end = min(k1, offL[d + 1]);

            // dual-sample pairs within this same-weight run
#pragma unroll 1
            for (; k + 1 < run_end; k += 2) {
                const int iA = lst[k];
                const int iB = lst[k + 1];
                const ulonglong2* vA = (const ulonglong2*)(v2f + (size_t)iA * VSTRIDE);
                const ulonglong2* vB = (const ulonglong2*)(v2f + (size_t)iB * VSTRIDE);
                u64 a0 = 0ull, a1 = 0ull, b0 = 0ull, b1 = 0ull;
                u64 c0 = 0ull, c1 = 0ull, e0 = 0ull, e1 = 0ull;
#pragma unroll
                for (int q = 0; q < 16; ++q) {
                    const ulonglong2 pA = vA[q];          // uniform LDS.128 (broadcast)
                    const ulonglong2 pB = vB[q];
                    a0 = ffma2(wa[2 * q + 0], pA.x, a0);
                    c0 = ffma2(wa[2 * q + 0], pB.x, c0);
                    b0 = ffma2(wb[2 * q + 0], pA.x, b0);
                    e0 = ffma2(wb[2 * q + 0], pB.x, e0);
                    a1 = ffma2(wa[2 * q + 1], pA.y, a1);
                    c1 = ffma2(wa[2 * q + 1], pB.y, c1);
                    b1 = ffma2(wb[2 * q + 1], pA.y, b1);
                    e1 = ffma2(wb[2 * q + 1], pB.y, e1);
                }
                float x0, x1, y0, y1;
                upk2(add2(a0, a1), x0, x1);
                upk2(add2(b0, b1), y0, y1);
                v2f[(size_t)iA * VSTRIDE + lane]      = x0 + x1;
                v2f[(size_t)iA * VSTRIDE + 32 + lane] = y0 + y1;
                upk2(add2(c0, c1), x0, x1);
                upk2(add2(e0, e1), y0, y1);
                v2f[(size_t)iB * VSTRIDE + lane]      = x0 + x1;
                v2f[(size_t)iB * VSTRIDE + 32 + lane] = y0 + y1;
            }
            // odd leftover in this run
            if (k < run_end) {
                const int iA = lst[k];
                const ulonglong2* vA = (const ulonglong2*)(v2f + (size_t)iA * VSTRIDE);
                u64 a0 = 0ull, a1 = 0ull, b0 = 0ull, b1 = 0ull;
#pragma unroll
                for (int q = 0; q < 16; ++q) {
                    const ulonglong2 pA = vA[q];
                    a0 = ffma2(wa[2 * q + 0], pA.x, a0);
                    b0 = ffma2(wb[2 * q + 0], pA.x, b0);
                    a1 = ffma2(wa[2 * q + 1], pA.y, a1);
                    b1 = ffma2(wb[2 * q + 1], pA.y, b1);
                }
                float x0, x1, y0, y1;
                upk2(add2(a0, a1), x0, x1);
                upk2(add2(b0, b1), y0, y1);
                v2f[(size_t)iA * VSTRIDE + lane]      = x0 + x1;
                v2f[(size_t)iA * VSTRIDE + 32 + lane] = y0 + y1;
                ++k;
            }
        }
        __syncthreads();
    }

    // ---- epilogue: thread t -> sample t: out = v @ P' (64x4), mask, store ----
    float o0 = 0.f, o1 = 0.f, o2 = 0.f, o3 = 0.f;
    {
        const float4* vrow = (const float4*)(v2f + (size_t)tid * VSTRIDE);
#pragma unroll
        for (int q = 0; q < 16; ++q) {
            const float4 t = vrow[q];
            const float4 p0 = *(const float4*)(pp + 4 * (4 * q + 0));
            const float4 p1 = *(const float4*)(pp + 4 * (4 * q + 1));
            const float4 p2 = *(const float4*)(pp + 4 * (4 * q + 2));
            const float4 p3 = *(const float4*)(pp + 4 * (4 * q + 3));
            o0 = fmaf(t.x, p0.x, o0); o1 = fmaf(t.x, p0.y, o1);
            o2 = fmaf(t.x, p0.z, o2); o3 = fmaf(t.x, p0.w, o3);
            o0 = fmaf(t.y, p1.x, o0); o1 = fmaf(t.y, p1.y, o1);
            o2 = fmaf(t.y, p1.z, o2); o3 = fmaf(t.y, p1.w, o3);
            o0 = fmaf(t.z, p2.x, o0); o1 = fmaf(t.z, p2.y, o1);
            o2 = fmaf(t.z, p2.z, o2); o3 = fmaf(t.z, p2.w, o3);
            o0 = fmaf(t.w, p3.x, o0); o1 = fmaf(t.w, p3.y, o1);
            o2 = fmaf(t.w, p3.z, o2); o3 = fmaf(t.w, p3.w, o3);
        }
    }
    out[3 * n + 0] = o0 * msk;
    out[3 * n + 1] = o1 * msk;
    out[3 * n + 2] = o2 * msk;
    out[3 * ntot + n] = o3 * msk;   // sigma block after rgb block
}

extern "C" void kernel_launch(void* const* d_in, const int* in_sizes, int n_in,
                              void* d_out, int out_size) {
    const float* coords   = (const float*)d_in[0];  // (B,R,3)
    const float* viewdirs = (const float*)d_in[1];  // (B,3)
    const float* core0    = (const float*)d_in[2];  // (1,8,64)
    const float* cores    = (const float*)d_in[3];  // (7,64,8,64)
    const float* payload  = (const float*)d_in[4];  // (64,28)

    const int B = in_sizes[1] / 3;   // 1024 (R = 256 = THREADS)

    cudaFuncSetAttribute(rftt_kernel, cudaFuncAttributeMaxDynamicSharedMemorySize, SM_BYTES);
    rftt_kernel<<<B, THREADS, SM_BYTES>>>(coords, viewdirs, core0, cores, payload, (float*)d_out);
}